// round 3
// baseline (speedup 1.0000x reference)
#include <cuda_runtime.h>
#include <math.h>

#define BATCH 1024
#define EMB   400
#define IMW   20
#define CH    96
#define RN    864
#define FH    18
#define FSZ   324
#define EPSV  1e-5f
#define NSET  6

typedef unsigned long long ull;

struct Ptr6 { const int* p[6]; };

// ---------------- packed f32x2 helpers (sm_103a) ----------------
__device__ __forceinline__ ull pk2(float lo, float hi) {
    ull d; asm("mov.b64 %0,{%1,%2};" : "=l"(d) : "f"(lo), "f"(hi)); return d;
}
__device__ __forceinline__ void upk2(ull v, float& lo, float& hi) {
    asm("mov.b64 {%0,%1},%2;" : "=f"(lo), "=f"(hi) : "l"(v));
}
__device__ __forceinline__ ull fma2(ull a, ull b, ull c) {
    ull d; asm("fma.rn.f32x2 %0,%1,%2,%3;" : "=l"(d) : "l"(a), "l"(b), "l"(c)); return d;
}
__device__ __forceinline__ ull add2(ull a, ull b) {
    ull d; asm("add.rn.f32x2 %0,%1,%2;" : "=l"(d) : "l"(a), "l"(b)); return d;
}
#define ABS2MASK 0x7fffffff7fffffffULL

// ---------------- device scratch (static, no allocation) ----------------
__device__ float d_rA[RN];            // r BN affine scale
__device__ float d_rC[RN];            // r BN affine shift
__device__ float d_eStat[NSET * 2];   // per-set e sum / sumsq
__device__ float d_chS[NSET * CH * 2];// per-set per-channel sum / sumsq
__device__ float d_sm[(long)NSET * BATCH * FSZ]; // softmax outputs

// ---------------- kernel 0: zero accumulators ----------------
__global__ void k_zero() {
    int i = threadIdx.x;
    if (i < NSET * 2) d_eStat[i] = 0.f;
    for (int j = i; j < NSET * CH * 2; j += blockDim.x) d_chS[j] = 0.f;
}

// ---------------- kernel 1: per-column BN affine for gathered R ----------------
__global__ void k_rstats(const int* __restrict__ r_idx, const float* __restrict__ R,
                         const float* __restrict__ g2, const float* __restrict__ b2) {
    int j = blockIdx.x;            // column 0..863
    float s = 0.f, ss = 0.f;
    for (int b = threadIdx.x; b < BATCH; b += blockDim.x) {
        float v = R[(long)r_idx[b] * RN + j];
        s += v; ss += v * v;
    }
    __shared__ float shs[8], shq[8];
    #pragma unroll
    for (int o = 16; o; o >>= 1) {
        s  += __shfl_xor_sync(0xffffffffu, s,  o);
        ss += __shfl_xor_sync(0xffffffffu, ss, o);
    }
    int w = threadIdx.x >> 5;
    if ((threadIdx.x & 31) == 0) { shs[w] = s; shq[w] = ss; }
    __syncthreads();
    if (threadIdx.x == 0) {
        float S = 0.f, Q = 0.f;
        int nw = blockDim.x >> 5;
        for (int k = 0; k < nw; k++) { S += shs[k]; Q += shq[k]; }
        float mu  = S / (float)BATCH;
        float var = Q / (float)BATCH - mu * mu;
        float a = g2[j] * rsqrtf(var + EPSV);
        d_rA[j] = a;
        d_rC[j] = b2[j] - mu * a;
    }
}

// ---------------- kernel 2: scalar e stats per set ----------------
__global__ void k_estats(Ptr6 eidx, const float* __restrict__ E) {
    int s = blockIdx.y;
    const int* ei = eidx.p[s];
    int chunk = blockIdx.x;                   // 32 samples per chunk
    float sum = 0.f, ssq = 0.f;
    for (int t = threadIdx.x; t < 32 * EMB; t += blockDim.x) {
        int b = chunk * 32 + t / EMB;
        int d = t % EMB;
        float v = E[(long)ei[b] * EMB + d];
        sum += v; ssq += v * v;
    }
    __shared__ float shs[8], shq[8];
    #pragma unroll
    for (int o = 16; o; o >>= 1) {
        sum += __shfl_xor_sync(0xffffffffu, sum, o);
        ssq += __shfl_xor_sync(0xffffffffu, ssq, o);
    }
    int w = threadIdx.x >> 5;
    if ((threadIdx.x & 31) == 0) { shs[w] = sum; shq[w] = ssq; }
    __syncthreads();
    if (threadIdx.x == 0) {
        float S = 0.f, Q = 0.f;
        int nw = blockDim.x >> 5;
        for (int k = 0; k < nw; k++) { S += shs[k]; Q += shq[k]; }
        atomicAdd(&d_eStat[s * 2 + 0], S);
        atomicAdd(&d_eStat[s * 2 + 1], Q);
    }
}

// ---------------- kernel 3: Gram-trick conv-channel stats ----------------
// Per (set, sample):  P[k] = sum_xy patch_k,  Q[k,k'] = sum_xy patch_k patch_k'
// Then per channel ch:  S1 += v.P,  S2 += v^T Q v  (v = normalized kernel row)
__global__ void k_gram(Ptr6 eidx, const int* __restrict__ r_idx,
                       const float* __restrict__ E, const float* __restrict__ R,
                       const float* __restrict__ g0, const float* __restrict__ b0) {
    int s = blockIdx.y, b = blockIdx.x, tid = threadIdx.x;
    __shared__ float eh[EMB];
    __shared__ float rh[CH * 9];
    __shared__ float red[4][54];
    __shared__ float Ps[9], Qs[81];

    float eS = d_eStat[s * 2 + 0], eQ = d_eStat[s * 2 + 1];
    float N0 = (float)(BATCH * EMB);
    float mu = eS / N0, var = eQ / N0 - mu * mu;
    float aE = g0[0] * rsqrtf(var + EPSV);
    float cE = b0[0] - mu * aE;

    const long erow = (long)eidx.p[s][b] * EMB;
    for (int i = tid; i < EMB; i += 128) eh[i] = fmaf(aE, E[erow + i], cE);
    const long rrow = (long)r_idx[b] * RN;
    for (int i = tid; i < RN; i += 128) rh[i] = fmaf(d_rA[i], R[rrow + i], d_rC[i]);
    __syncthreads();

    float P[9]; float Q[45];
    #pragma unroll
    for (int k = 0; k < 9; k++) P[k] = 0.f;
    #pragma unroll
    for (int k = 0; k < 45; k++) Q[k] = 0.f;

    for (int p = tid; p < FSZ; p += 128) {
        int ox = p / FH, oy = p % FH;
        const float* base = &eh[ox * IMW + oy];
        float v[9];
        #pragma unroll
        for (int di = 0; di < 3; di++)
            #pragma unroll
            for (int dj = 0; dj < 3; dj++)
                v[di * 3 + dj] = base[di * IMW + dj];
        int q = 0;
        #pragma unroll
        for (int k = 0; k < 9; k++) {
            P[k] += v[k];
            #pragma unroll
            for (int k2 = k; k2 < 9; k2++) Q[q++] += v[k] * v[k2];
        }
    }
    // warp reduce the 54 partials
    #pragma unroll
    for (int o = 16; o; o >>= 1) {
        #pragma unroll
        for (int k = 0; k < 9; k++)  P[k] += __shfl_xor_sync(0xffffffffu, P[k], o);
        #pragma unroll
        for (int k = 0; k < 45; k++) Q[k] += __shfl_xor_sync(0xffffffffu, Q[k], o);
    }
    int w = tid >> 5;
    if ((tid & 31) == 0) {
        #pragma unroll
        for (int k = 0; k < 9; k++)  red[w][k] = P[k];
        #pragma unroll
        for (int k = 0; k < 45; k++) red[w][9 + k] = Q[k];
    }
    __syncthreads();
    if (tid < 54) {
        float v = red[0][tid] + red[1][tid] + red[2][tid] + red[3][tid];
        if (tid < 9) Ps[tid] = v;
        else {
            int li = tid - 9, k = 0, rem = li;
            while (rem >= 9 - k) { rem -= 9 - k; k++; }
            int k2 = k + rem;
            Qs[k * 9 + k2] = v;
            Qs[k2 * 9 + k] = v;
        }
    }
    __syncthreads();
    if (tid < CH) {
        float v[9];
        #pragma unroll
        for (int k = 0; k < 9; k++) v[k] = rh[tid * 9 + k];
        float s1 = 0.f, s2 = 0.f;
        #pragma unroll
        for (int k = 0; k < 9; k++) {
            s1 = fmaf(v[k], Ps[k], s1);
            float t = 0.f;
            #pragma unroll
            for (int k2 = 0; k2 < 9; k2++) t = fmaf(v[k2], Qs[k * 9 + k2], t);
            s2 = fmaf(v[k], t, s2);
        }
        atomicAdd(&d_chS[(s * CH + tid) * 2 + 0], s1);
        atomicAdd(&d_chS[(s * CH + tid) * 2 + 1], s2);
    }
}

// ---------------- kernel 4: conv + BN + relu + channel-sum + softmax ----------------
// 96 threads, 4 pixels/thread via two f32x2 accumulators.
// BN folded into weights: w'_k = (a/2) w_k, c' = c/2; y = sum w'_k v_k + c'
// relu(a*x+c) = y + |y|  (exact in fp32).
__global__ void __launch_bounds__(96) k_final(
        Ptr6 eidx, const int* __restrict__ r_idx,
        const float* __restrict__ E, const float* __restrict__ R,
        const float* __restrict__ g0, const float* __restrict__ b0,
        const float* __restrict__ g1, const float* __restrict__ b1) {
    int s = blockIdx.y, b = blockIdx.x, tid = threadIdx.x;
    float* smrow = &d_sm[((long)s * BATCH + b) * FSZ];
    const int row = eidx.p[s][b];
    if (row == 0) {   // padding entity: softmax of constant row = uniform
        for (int i = tid; i < FSZ; i += 96) smrow[i] = 1.0f / (float)FSZ;
        return;
    }
    __shared__ float eh[EMB];
    __shared__ __align__(16) ull rpk[CH][12];  // [w'0..w'8, c', pad, pad]
    __shared__ float aH[CH];
    __shared__ float redm[3], reds[3];

    float eS = d_eStat[s * 2 + 0], eQ = d_eStat[s * 2 + 1];
    float N0 = (float)(BATCH * EMB);
    float mu = eS / N0, var = eQ / N0 - mu * mu;
    float aE = g0[0] * rsqrtf(var + EPSV);
    float cE = b0[0] - mu * aE;

    const long erow = (long)row * EMB;
    for (int i = tid; i < EMB; i += 96) eh[i] = fmaf(aE, E[erow + i], cE);
    if (tid < CH) {
        float S1 = d_chS[(s * CH + tid) * 2 + 0];
        float S2 = d_chS[(s * CH + tid) * 2 + 1];
        float Nn = (float)(BATCH * FSZ);
        float m1 = S1 / Nn, v1 = S2 / Nn - m1 * m1;
        float a = g1[tid] * rsqrtf(v1 + EPSV);
        float c = b1[tid] - m1 * a;
        aH[tid] = 0.5f * a;
        rpk[tid][9] = pk2(0.5f * c, 0.5f * c);
    }
    __syncthreads();
    const long rrow = (long)r_idx[b] * RN;
    for (int i = tid; i < RN; i += 96) {
        float rv = fmaf(d_rA[i], R[rrow + i], d_rC[i]) * aH[i / 9];
        rpk[i / 9][i % 9] = pk2(rv, rv);
    }
    __syncthreads();

    // four pixels: tid, tid+96, tid+192, tid+288(guarded: tid<36)
    const bool has3 = (tid < FSZ - 288);
    int p0 = tid, p1 = tid + 96, p2 = tid + 192, p3 = has3 ? tid + 288 : 0;
    ull vA[9], vB[9];   // vA = (pix0, pix1), vB = (pix2, pix3)
    {
        const float* b0p = &eh[(p0 / FH) * IMW + (p0 % FH)];
        const float* b1p = &eh[(p1 / FH) * IMW + (p1 % FH)];
        const float* b2p = &eh[(p2 / FH) * IMW + (p2 % FH)];
        const float* b3p = &eh[(p3 / FH) * IMW + (p3 % FH)];
        #pragma unroll
        for (int di = 0; di < 3; di++)
            #pragma unroll
            for (int dj = 0; dj < 3; dj++) {
                int k = di * 3 + dj, o = di * IMW + dj;
                vA[k] = pk2(b0p[o], b1p[o]);
                vB[k] = pk2(b2p[o], b3p[o]);
            }
    }

    ull tAp = 0, tAa = 0, tBp = 0, tBa = 0;  // sum(y) and sum(|y|)
    #pragma unroll 2
    for (int ch = 0; ch < CH; ch++) {
        const ulonglong2* rw = (const ulonglong2*)&rpk[ch][0];
        ulonglong2 w01 = rw[0], w23 = rw[1], w45 = rw[2], w67 = rw[3];
        ulonglong2 w8c = rw[4];                // {w'8, c'}
        ull y0 = w8c.y, y1 = w8c.y;            // seed with c'
        y0 = fma2(w01.x, vA[0], y0); y1 = fma2(w01.x, vB[0], y1);
        y0 = fma2(w01.y, vA[1], y0); y1 = fma2(w01.y, vB[1], y1);
        y0 = fma2(w23.x, vA[2], y0); y1 = fma2(w23.x, vB[2], y1);
        y0 = fma2(w23.y, vA[3], y0); y1 = fma2(w23.y, vB[3], y1);
        y0 = fma2(w45.x, vA[4], y0); y1 = fma2(w45.x, vB[4], y1);
        y0 = fma2(w45.y, vA[5], y0); y1 = fma2(w45.y, vB[5], y1);
        y0 = fma2(w67.x, vA[6], y0); y1 = fma2(w67.x, vB[6], y1);
        y0 = fma2(w67.y, vA[7], y0); y1 = fma2(w67.y, vB[7], y1);
        y0 = fma2(w8c.x, vA[8], y0); y1 = fma2(w8c.x, vB[8], y1);
        tAp = add2(tAp, y0); tAa = add2(tAa, y0 & ABS2MASK);
        tBp = add2(tBp, y1); tBa = add2(tBa, y1 & ABS2MASK);
    }
    ull tA = add2(tAp, tAa), tB = add2(tBp, tBa);
    float t0, t1, t2, t3;
    upk2(tA, t0, t1);
    upk2(tB, t2, t3);
    if (!has3) t3 = -INFINITY;

    // softmax over 324 logits (3 warps)
    float m = fmaxf(fmaxf(t0, t1), fmaxf(t2, t3));
    #pragma unroll
    for (int o = 16; o; o >>= 1) m = fmaxf(m, __shfl_xor_sync(0xffffffffu, m, o));
    int w = tid >> 5;
    if ((tid & 31) == 0) redm[w] = m;
    __syncthreads();
    m = fmaxf(fmaxf(redm[0], redm[1]), redm[2]);

    float e0 = __expf(t0 - m);
    float e1 = __expf(t1 - m);
    float e2 = __expf(t2 - m);
    float e3 = has3 ? __expf(t3 - m) : 0.f;
    float ssum = (e0 + e1) + (e2 + e3);
    #pragma unroll
    for (int o = 16; o; o >>= 1) ssum += __shfl_xor_sync(0xffffffffu, ssum, o);
    if ((tid & 31) == 0) reds[w] = ssum;
    __syncthreads();
    float S = reds[0] + reds[1] + reds[2];
    float inv = 1.f / S;
    smrow[p0] = e0 * inv;
    smrow[p1] = e1 * inv;
    smrow[p2] = e2 * inv;
    if (has3) smrow[tid + 288] = e3 * inv;
}

// ---------------- kernel 5: 6-way product and dot with p ----------------
__global__ void k_out(const float* __restrict__ p, float* __restrict__ out) {
    int b = blockIdx.x, tid = threadIdx.x;
    float acc = 0.f;
    for (int i = tid; i < FSZ; i += 128) {
        float v = d_sm[((long)0 * BATCH + b) * FSZ + i];
        #pragma unroll
        for (int s = 1; s < NSET; s++)
            v *= d_sm[((long)s * BATCH + b) * FSZ + i];
        acc = fmaf(v, p[i], acc);
    }
    __shared__ float sh[4];
    #pragma unroll
    for (int o = 16; o; o >>= 1) acc += __shfl_xor_sync(0xffffffffu, acc, o);
    int w = tid >> 5;
    if ((tid & 31) == 0) sh[w] = acc;
    __syncthreads();
    if (tid == 0) out[b] = sh[0] + sh[1] + sh[2] + sh[3];
}

// ---------------- launch ----------------
extern "C" void kernel_launch(void* const* d_in, const int* in_sizes, int n_in,
                              void* d_out, int out_size) {
    const int* r_idx = (const int*)d_in[0];
    Ptr6 e;
    for (int i = 0; i < 6; i++) e.p[i] = (const int*)d_in[1 + i];
    const float* E  = (const float*)d_in[7];
    const float* R  = (const float*)d_in[8];
    const float* g0 = (const float*)d_in[9];
    const float* b0 = (const float*)d_in[10];
    const float* g1 = (const float*)d_in[11];
    const float* b1 = (const float*)d_in[12];
    const float* g2 = (const float*)d_in[13];
    const float* b2 = (const float*)d_in[14];
    const float* p  = (const float*)d_in[15];
    float* out = (float*)d_out;

    k_zero<<<1, 256>>>();
    k_rstats<<<RN, 256>>>(r_idx, R, g2, b2);
    k_estats<<<dim3(32, NSET), 256>>>(e, E);
    k_gram<<<dim3(BATCH, NSET), 128>>>(e, r_idx, E, R, g0, b0);
    k_final<<<dim3(BATCH, NSET), 96>>>(e, r_idx, E, R, g0, b0, g1, b1);
    k_out<<<BATCH, 128>>>(p, out);
}

// round 12
// speedup vs baseline: 1.2006x; 1.2006x over previous
#include <cuda_runtime.h>
#include <math.h>

#define BATCH 1024
#define EMB   400
#define IMW   20
#define CH    96
#define RN    864
#define FH    18
#define FSZ   324
#define EPSV  1e-5f
#define NSET  6

typedef unsigned long long ull;

struct Ptr6 { const int* p[6]; };

// ---------------- packed f32x2 helpers (sm_103a) ----------------
__device__ __forceinline__ ull pk2(float lo, float hi) {
    ull d; asm("mov.b64 %0,{%1,%2};" : "=l"(d) : "f"(lo), "f"(hi)); return d;
}
__device__ __forceinline__ void upk2(ull v, float& lo, float& hi) {
    asm("mov.b64 {%0,%1},%2;" : "=f"(lo), "=f"(hi) : "l"(v));
}
__device__ __forceinline__ ull fma2(ull a, ull b, ull c) {
    ull d; asm("fma.rn.f32x2 %0,%1,%2,%3;" : "=l"(d) : "l"(a), "l"(b), "l"(c)); return d;
}
__device__ __forceinline__ ull add2(ull a, ull b) {
    ull d; asm("add.rn.f32x2 %0,%1,%2;" : "=l"(d) : "l"(a), "l"(b)); return d;
}
#define ABS2MASK 0x7fffffff7fffffffULL

// ---------------- device scratch (static, no allocation) ----------------
__device__ float d_rA[RN];            // r BN affine scale
__device__ float d_rC[RN];            // r BN affine shift
__device__ float d_eStat[NSET * 2];   // per-set e sum / sumsq
__device__ float d_chS[NSET * CH * 2];// per-set per-channel sum / sumsq
__device__ float d_sm[(long)NSET * BATCH * FSZ]; // softmax outputs

// ---------------- kernel 0: zero accumulators ----------------
__global__ void k_zero() {
    int i = threadIdx.x;
    if (i < NSET * 2) d_eStat[i] = 0.f;
    for (int j = i; j < NSET * CH * 2; j += blockDim.x) d_chS[j] = 0.f;
}

// ---------------- kernel 1: per-column BN affine for gathered R ----------------
__global__ void k_rstats(const int* __restrict__ r_idx, const float* __restrict__ R,
                         const float* __restrict__ g2, const float* __restrict__ b2) {
    int j = blockIdx.x;            // column 0..863
    float s = 0.f, ss = 0.f;
    for (int b = threadIdx.x; b < BATCH; b += blockDim.x) {
        float v = R[(long)r_idx[b] * RN + j];
        s += v; ss += v * v;
    }
    __shared__ float shs[8], shq[8];
    #pragma unroll
    for (int o = 16; o; o >>= 1) {
        s  += __shfl_xor_sync(0xffffffffu, s,  o);
        ss += __shfl_xor_sync(0xffffffffu, ss, o);
    }
    int w = threadIdx.x >> 5;
    if ((threadIdx.x & 31) == 0) { shs[w] = s; shq[w] = ss; }
    __syncthreads();
    if (threadIdx.x == 0) {
        float S = 0.f, Q = 0.f;
        int nw = blockDim.x >> 5;
        for (int k = 0; k < nw; k++) { S += shs[k]; Q += shq[k]; }
        float mu  = S / (float)BATCH;
        float var = Q / (float)BATCH - mu * mu;
        float a = g2[j] * rsqrtf(var + EPSV);
        d_rA[j] = a;
        d_rC[j] = b2[j] - mu * a;
    }
}

// ---------------- kernel 2: scalar e stats per set ----------------
__global__ void k_estats(Ptr6 eidx, const float* __restrict__ E) {
    int s = blockIdx.y;
    const int* ei = eidx.p[s];
    int chunk = blockIdx.x;                   // 32 samples per chunk
    float sum = 0.f, ssq = 0.f;
    for (int t = threadIdx.x; t < 32 * EMB; t += blockDim.x) {
        int b = chunk * 32 + t / EMB;
        int d = t % EMB;
        float v = E[(long)ei[b] * EMB + d];
        sum += v; ssq += v * v;
    }
    __shared__ float shs[8], shq[8];
    #pragma unroll
    for (int o = 16; o; o >>= 1) {
        sum += __shfl_xor_sync(0xffffffffu, sum, o);
        ssq += __shfl_xor_sync(0xffffffffu, ssq, o);
    }
    int w = threadIdx.x >> 5;
    if ((threadIdx.x & 31) == 0) { shs[w] = sum; shq[w] = ssq; }
    __syncthreads();
    if (threadIdx.x == 0) {
        float S = 0.f, Q = 0.f;
        int nw = blockDim.x >> 5;
        for (int k = 0; k < nw; k++) { S += shs[k]; Q += shq[k]; }
        atomicAdd(&d_eStat[s * 2 + 0], S);
        atomicAdd(&d_eStat[s * 2 + 1], Q);
    }
}

// ---------------- kernel 3: Gram-trick conv-channel stats (warp-per-sample) ----
// Per sample: P[k] = sum_xy patch_k, Q[k,k'] = sum_xy patch_k patch_k'.
// One warp owns one sample; butterfly leaves full P/Q in every lane, so the
// per-channel phase (s1 = v.P, s2 = v^T Q v) runs from registers with no
// block-level sync at all.
__global__ void __launch_bounds__(128) k_gram(
        Ptr6 eidx, const int* __restrict__ r_idx,
        const float* __restrict__ E, const float* __restrict__ R,
        const float* __restrict__ g0, const float* __restrict__ b0) {
    int s = blockIdx.y;
    int warp = threadIdx.x >> 5, lane = threadIdx.x & 31;
    int b = blockIdx.x * 4 + warp;
    __shared__ float eh[4][EMB];

    float eS = d_eStat[s * 2 + 0], eQ = d_eStat[s * 2 + 1];
    float N0 = (float)(BATCH * EMB);
    float mu = eS / N0, var = eQ / N0 - mu * mu;
    float aE = g0[0] * rsqrtf(var + EPSV);
    float cE = b0[0] - mu * aE;

    const long erow = (long)eidx.p[s][b] * EMB;
    for (int i = lane; i < EMB; i += 32) eh[warp][i] = fmaf(aE, E[erow + i], cE);
    __syncwarp();

    float P[9], Q[45];
    #pragma unroll
    for (int k = 0; k < 9; k++) P[k] = 0.f;
    #pragma unroll
    for (int k = 0; k < 45; k++) Q[k] = 0.f;

    for (int p = lane; p < FSZ; p += 32) {
        int ox = p / FH, oy = p % FH;
        const float* base = &eh[warp][ox * IMW + oy];
        float v[9];
        #pragma unroll
        for (int di = 0; di < 3; di++)
            #pragma unroll
            for (int dj = 0; dj < 3; dj++)
                v[di * 3 + dj] = base[di * IMW + dj];
        int q = 0;
        #pragma unroll
        for (int k = 0; k < 9; k++) {
            P[k] += v[k];
            #pragma unroll
            for (int k2 = k; k2 < 9; k2++) Q[q++] += v[k] * v[k2];
        }
    }
    // one butterfly per sample; afterwards every lane holds the full sums
    #pragma unroll
    for (int o = 16; o; o >>= 1) {
        #pragma unroll
        for (int k = 0; k < 9; k++)  P[k] += __shfl_xor_sync(0xffffffffu, P[k], o);
        #pragma unroll
        for (int k = 0; k < 45; k++) Q[k] += __shfl_xor_sync(0xffffffffu, Q[k], o);
    }

    // per-channel phase: 3 channels per lane, straight from registers
    const long rrow = (long)r_idx[b] * RN;
    #pragma unroll
    for (int c = 0; c < 3; c++) {
        int ch = lane + 32 * c;
        float v[9];
        #pragma unroll
        for (int k = 0; k < 9; k++) {
            int i = ch * 9 + k;
            v[k] = fmaf(d_rA[i], R[rrow + i], d_rC[i]);
        }
        float s1 = 0.f, s2 = 0.f;
        int q = 0;
        #pragma unroll
        for (int k = 0; k < 9; k++) {
            s1 = fmaf(v[k], P[k], s1);
            s2 = fmaf(Q[q++] * v[k], v[k], s2);       // diagonal
            float v2 = v[k] + v[k];
            #pragma unroll
            for (int k2 = k + 1; k2 < 9; k2++)
                s2 = fmaf(Q[q++] * v2, v[k2], s2);    // off-diagonal (x2)
        }
        atomicAdd(&d_chS[(s * CH + ch) * 2 + 0], s1);
        atomicAdd(&d_chS[(s * CH + ch) * 2 + 1], s2);
    }
}

// ---------------- kernel 4: conv + BN + relu + channel-sum + softmax ----------------
// 96 threads, 4 pixels/thread via two f32x2 accumulators.
// BN folded into weights: w'_k = (a/2) w_k, c' = c/2; y = sum w'_k v_k + c'
// relu(a*x+c) = y + |y|  (exact in fp32).
__global__ void __launch_bounds__(96) k_final(
        Ptr6 eidx, const int* __restrict__ r_idx,
        const float* __restrict__ E, const float* __restrict__ R,
        const float* __restrict__ g0, const float* __restrict__ b0,
        const float* __restrict__ g1, const float* __restrict__ b1) {
    int s = blockIdx.y, b = blockIdx.x, tid = threadIdx.x;
    float* smrow = &d_sm[((long)s * BATCH + b) * FSZ];
    const int row = eidx.p[s][b];
    if (row == 0) {   // padding entity: softmax of constant row = uniform
        for (int i = tid; i < FSZ; i += 96) smrow[i] = 1.0f / (float)FSZ;
        return;
    }
    __shared__ float eh[EMB];
    __shared__ __align__(16) ull rpk[CH][12];  // [w'0..w'8, c', pad, pad]
    __shared__ float aH[CH];
    __shared__ float redm[3], reds[3];

    float eS = d_eStat[s * 2 + 0], eQ = d_eStat[s * 2 + 1];
    float N0 = (float)(BATCH * EMB);
    float mu = eS / N0, var = eQ / N0 - mu * mu;
    float aE = g0[0] * rsqrtf(var + EPSV);
    float cE = b0[0] - mu * aE;

    const long erow = (long)row * EMB;
    for (int i = tid; i < EMB; i += 96) eh[i] = fmaf(aE, E[erow + i], cE);
    if (tid < CH) {
        float S1 = d_chS[(s * CH + tid) * 2 + 0];
        float S2 = d_chS[(s * CH + tid) * 2 + 1];
        float Nn = (float)(BATCH * FSZ);
        float m1 = S1 / Nn, v1 = S2 / Nn - m1 * m1;
        float a = g1[tid] * rsqrtf(v1 + EPSV);
        float c = b1[tid] - m1 * a;
        aH[tid] = 0.5f * a;
        rpk[tid][9] = pk2(0.5f * c, 0.5f * c);
    }
    __syncthreads();
    const long rrow = (long)r_idx[b] * RN;
    for (int i = tid; i < RN; i += 96) {
        float rv = fmaf(d_rA[i], R[rrow + i], d_rC[i]) * aH[i / 9];
        rpk[i / 9][i % 9] = pk2(rv, rv);
    }
    __syncthreads();

    // four pixels: tid, tid+96, tid+192, tid+288(guarded: tid<36)
    const bool has3 = (tid < FSZ - 288);
    int p0 = tid, p1 = tid + 96, p2 = tid + 192, p3 = has3 ? tid + 288 : 0;
    ull vA[9], vB[9];   // vA = (pix0, pix1), vB = (pix2, pix3)
    {
        const float* b0p = &eh[(p0 / FH) * IMW + (p0 % FH)];
        const float* b1p = &eh[(p1 / FH) * IMW + (p1 % FH)];
        const float* b2p = &eh[(p2 / FH) * IMW + (p2 % FH)];
        const float* b3p = &eh[(p3 / FH) * IMW + (p3 % FH)];
        #pragma unroll
        for (int di = 0; di < 3; di++)
            #pragma unroll
            for (int dj = 0; dj < 3; dj++) {
                int k = di * 3 + dj, o = di * IMW + dj;
                vA[k] = pk2(b0p[o], b1p[o]);
                vB[k] = pk2(b2p[o], b3p[o]);
            }
    }

    ull tAp = 0, tAa = 0, tBp = 0, tBa = 0;  // sum(y) and sum(|y|)
    #pragma unroll 2
    for (int ch = 0; ch < CH; ch++) {
        const ulonglong2* rw = (const ulonglong2*)&rpk[ch][0];
        ulonglong2 w01 = rw[0], w23 = rw[1], w45 = rw[2], w67 = rw[3];
        ulonglong2 w8c = rw[4];                // {w'8, c'}
        ull y0 = w8c.y, y1 = w8c.y;            // seed with c'
        y0 = fma2(w01.x, vA[0], y0); y1 = fma2(w01.x, vB[0], y1);
        y0 = fma2(w01.y, vA[1], y0); y1 = fma2(w01.y, vB[1], y1);
        y0 = fma2(w23.x, vA[2], y0); y1 = fma2(w23.x, vB[2], y1);
        y0 = fma2(w23.y, vA[3], y0); y1 = fma2(w23.y, vB[3], y1);
        y0 = fma2(w45.x, vA[4], y0); y1 = fma2(w45.x, vB[4], y1);
        y0 = fma2(w45.y, vA[5], y0); y1 = fma2(w45.y, vB[5], y1);
        y0 = fma2(w67.x, vA[6], y0); y1 = fma2(w67.x, vB[6], y1);
        y0 = fma2(w67.y, vA[7], y0); y1 = fma2(w67.y, vB[7], y1);
        y0 = fma2(w8c.x, vA[8], y0); y1 = fma2(w8c.x, vB[8], y1);
        tAp = add2(tAp, y0); tAa = add2(tAa, y0 & ABS2MASK);
        tBp = add2(tBp, y1); tBa = add2(tBa, y1 & ABS2MASK);
    }
    ull tA = add2(tAp, tAa), tB = add2(tBp, tBa);
    float t0, t1, t2, t3;
    upk2(tA, t0, t1);
    upk2(tB, t2, t3);
    if (!has3) t3 = -INFINITY;

    // softmax over 324 logits (3 warps)
    float m = fmaxf(fmaxf(t0, t1), fmaxf(t2, t3));
    #pragma unroll
    for (int o = 16; o; o >>= 1) m = fmaxf(m, __shfl_xor_sync(0xffffffffu, m, o));
    int w = tid >> 5;
    if ((tid & 31) == 0) redm[w] = m;
    __syncthreads();
    m = fmaxf(fmaxf(redm[0], redm[1]), redm[2]);

    float e0 = __expf(t0 - m);
    float e1 = __expf(t1 - m);
    float e2 = __expf(t2 - m);
    float e3 = has3 ? __expf(t3 - m) : 0.f;
    float ssum = (e0 + e1) + (e2 + e3);
    #pragma unroll
    for (int o = 16; o; o >>= 1) ssum += __shfl_xor_sync(0xffffffffu, ssum, o);
    if ((tid & 31) == 0) reds[w] = ssum;
    __syncthreads();
    float S = reds[0] + reds[1] + reds[2];
    float inv = 1.f / S;
    smrow[p0] = e0 * inv;
    smrow[p1] = e1 * inv;
    smrow[p2] = e2 * inv;
    if (has3) smrow[tid + 288] = e3 * inv;
}

// ---------------- kernel 5: 6-way product and dot with p ----------------
__global__ void k_out(const float* __restrict__ p, float* __restrict__ out) {
    int b = blockIdx.x, tid = threadIdx.x;
    float acc = 0.f;
    for (int i = tid; i < FSZ; i += 128) {
        float v = d_sm[((long)0 * BATCH + b) * FSZ + i];
        #pragma unroll
        for (int s = 1; s < NSET; s++)
            v *= d_sm[((long)s * BATCH + b) * FSZ + i];
        acc = fmaf(v, p[i], acc);
    }
    __shared__ float sh[4];
    #pragma unroll
    for (int o = 16; o; o >>= 1) acc += __shfl_xor_sync(0xffffffffu, acc, o);
    int w = tid >> 5;
    if ((tid & 31) == 0) sh[w] = acc;
    __syncthreads();
    if (tid == 0) out[b] = sh[0] + sh[1] + sh[2] + sh[3];
}

// ---------------- launch ----------------
extern "C" void kernel_launch(void* const* d_in, const int* in_sizes, int n_in,
                              void* d_out, int out_size) {
    const int* r_idx = (const int*)d_in[0];
    Ptr6 e;
    for (int i = 0; i < 6; i++) e.p[i] = (const int*)d_in[1 + i];
    const float* E  = (const float*)d_in[7];
    const float* R  = (const float*)d_in[8];
    const float* g0 = (const float*)d_in[9];
    const float* b0 = (const float*)d_in[10];
    const float* g1 = (const float*)d_in[11];
    const float* b1 = (const float*)d_in[12];
    const float* g2 = (const float*)d_in[13];
    const float* b2 = (const float*)d_in[14];
    const float* p  = (const float*)d_in[15];
    float* out = (float*)d_out;

    k_zero<<<1, 256>>>();
    k_rstats<<<RN, 256>>>(r_idx, R, g2, b2);
    k_estats<<<dim3(32, NSET), 256>>>(e, E);
    k_gram<<<dim3(256, NSET), 128>>>(e, r_idx, E, R, g0, b0);
    k_final<<<dim3(BATCH, NSET), 96>>>(e, r_idx, E, R, g0, b0, g1, b1);
    k_out<<<BATCH, 128>>>(p, out);
}